// round 16
// baseline (speedup 1.0000x reference)
#include <cuda_runtime.h>
#include <cstdint>

#define NT 384
#define NW 12
#define WU 512
#define WCOLS 1536
#define GP 240   // phases grid (720 jobs x 4 row-quarters = 2880 warps)
#define GC 192   // chain grid (48 col-blocks x 4 row-quarters)
#define CL 16    // GRU0 cluster size
#define GT 256   // GRU0 threads per CTA (8 warps, 4 units/warp)

typedef unsigned long long u64;

// ---------------- device scratch (static, no allocation) ----------------
__device__ float g_bufA[16 * WU];
__device__ float g_bufB[16 * WU];
__device__ float g_h1[15 * WU];
__device__ float g_ghp[15 * WCOLS];
__device__ float g_gxc[15 * WCOLS];
__device__ float g_gpart[8 * WCOLS];   // [ci&1][qtr][col]
__device__ unsigned g_cnt_grp[32];
__device__ unsigned g_cnt_root;
__device__ unsigned g_gen;

// Tree grid barrier: 8-CTA leaf groups -> root. All counters return to 0
// before g_gen publishes, so the zero-init invariant holds across launches.
__device__ __forceinline__ void grid_sync_tree(unsigned &gen, unsigned ngrp) {
  unsigned next = gen + 1u;
  __threadfence();
  __syncthreads();
  if (threadIdx.x == 0) {
    unsigned g = (unsigned)blockIdx.x >> 3;
    bool last = false;
    if (atomicAdd(&g_cnt_grp[g], 1u) == 7u) {
      if (atomicAdd(&g_cnt_root, 1u) == ngrp - 1u) last = true;
    }
    if (last) {
      for (unsigned i = 0; i < ngrp; ++i) g_cnt_grp[i] = 0u;
      g_cnt_root = 0u;
      __threadfence();
      atomicExch(&g_gen, next);
    } else {
      while ((int)(*(volatile unsigned *)&g_gen - next) < 0) { }
    }
  }
  gen = next;
  __syncthreads();
}

__device__ __forceinline__ float sigmoidf_(float x) {
  return 1.0f / (1.0f + __expf(-x));
}
__device__ __forceinline__ float tanhf_(float x) {
  float ax = fabsf(x);
  float e = __expf(-2.0f * ax);
  float t = (1.0f - e) / (1.0f + e);
  return copysignf(t, x);
}
__device__ __forceinline__ float sigf_fast(float x) {
  return __fdividef(1.0f, 1.0f + __expf(-x));
}
__device__ __forceinline__ float tanhf_fast(float x) {
  float ax = fabsf(x);
  float e = __expf(-2.0f * ax);
  float t = __fdividef(1.0f - e, 1.0f + e);
  return copysignf(t, x);
}

// ---------------- Blackwell helpers ----------------
__device__ __forceinline__ void ffma2(u64 &acc, u64 a, u64 b) {
  asm("fma.rn.f32x2 %0, %1, %2, %0;" : "+l"(acc) : "l"(a), "l"(b));
}
__device__ __forceinline__ float hsum2(u64 v) {
  float lo, hi;
  asm("mov.b64 {%0,%1}, %2;" : "=f"(lo), "=f"(hi) : "l"(v));
  return lo + hi;
}
__device__ __forceinline__ uint32_t mapa_u32(uint32_t laddr, unsigned rank) {
  uint32_t raddr;
  asm("mapa.shared::cluster.u32 %0, %1, %2;" : "=r"(raddr) : "r"(laddr), "r"(rank));
  return raddr;
}
__device__ __forceinline__ void st_async_b64(uint32_t raddr, uint32_t rmbar, u64 v) {
  asm volatile(
      "st.async.shared::cluster.mbarrier::complete_tx::bytes.b64 [%0], %1, [%2];"
      :: "r"(raddr), "l"(v), "r"(rmbar) : "memory");
}
__device__ __forceinline__ void mbar_init(uint32_t mbar, unsigned cnt) {
  asm volatile("mbarrier.init.shared.b64 [%0], %1;" :: "r"(mbar), "r"(cnt) : "memory");
}
__device__ __forceinline__ void mbar_expect_tx(uint32_t mbar, unsigned bytes) {
  asm volatile("mbarrier.arrive.expect_tx.shared.b64 _, [%0], %1;"
               :: "r"(mbar), "r"(bytes) : "memory");
}
__device__ __forceinline__ void mbar_wait(uint32_t mbar, uint32_t parity) {
  uint32_t done;
  asm volatile(
      "{\n\t.reg .pred p;\n\t"
      "mbarrier.try_wait.parity.acquire.cta.shared::cta.b64 p, [%1], %2;\n\t"
      "selp.b32 %0, 1, 0, p;\n\t}"
      : "=r"(done) : "r"(mbar), "r"(parity) : "memory");
  if (!done) {
    asm volatile(
        "{\n\t.reg .pred P1;\n\t"
        "WAIT_LOOP_%=:\n\t"
        "mbarrier.try_wait.parity.acquire.cta.shared::cta.b64 P1, [%0], %1, 0x989680;\n\t"
        "@P1 bra.uni WAIT_DONE_%=;\n\t"
        "bra.uni WAIT_LOOP_%=;\n\t"
        "WAIT_DONE_%=:\n\t}"
        :: "r"(mbar), "r"(parity) : "memory");
  }
}
__device__ __forceinline__ void cluster_sync_() {
  asm volatile("barrier.cluster.arrive.aligned;" ::: "memory");
  asm volatile("barrier.cluster.wait.aligned;" ::: "memory");
}

// =====================================================================
// Phases kernel (GP=240 CTAs, 2/SM): gxc -> h1 -> ghp for all 15 chain GRUs
// Each of the 720 column jobs split into 4 row-quarters (4 warps/job).
// rkc is read-once -> __ldcs (evict-first) so kc stays resident in L2
// for the chain kernel's re-reads.
// =====================================================================
__global__ void __launch_bounds__(NT, 2) phases_kernel(
    const float *__restrict__ lin, const float *__restrict__ kc,
    const float *__restrict__ rkc, const float *__restrict__ bc)
{
  __shared__ float sm_x1[WU];
  __shared__ float sm_part[NW][32];
  const int bid = blockIdx.x, tid = threadIdx.x;
  const int warp = tid >> 5, lane = tid & 31;
  unsigned gen = *(volatile unsigned *)&g_gen;

  for (int i = tid; i < WU; i += NT) sm_x1[i] = __ldcg(lin + i * 16 + 1);
  __syncthreads();

  const int wg = bid * NW + warp;        // 0..2879
  const int job = wg >> 2, qtr = wg & 3; // 720 jobs x 4 quarters
  const int ci = job / 48;
  const int col = (job - ci * 48) * 32 + lane;

  // phase A: gxc[ci][col] = x1 . kc[ci][:,col] + b_i  (row-quarter split)
  {
    const float *wp = kc + (size_t)ci * (WU * WCOLS) + (size_t)(qtr * 128) * WCOLS + col;
    float a[16];
#pragma unroll
    for (int j = 0; j < 16; ++j) a[j] = 0.0f;
    for (int r = 0; r < 128; r += 16) {
#pragma unroll
      for (int j = 0; j < 16; ++j)
        a[j] = fmaf(sm_x1[qtr * 128 + r + j], __ldg(wp + (size_t)(r + j) * WCOLS), a[j]);
    }
    float s = 0.0f;
#pragma unroll
    for (int j = 0; j < 16; ++j) s += a[j];
    sm_part[warp][lane] = s;
    __syncthreads();
    if ((warp & 3) == 0) {
      float tot = sm_part[warp][lane] + sm_part[warp + 1][lane] +
                  sm_part[warp + 2][lane] + sm_part[warp + 3][lane];
      g_gxc[ci * WCOLS + col] = tot + __ldg(bc + ci * 3072 + col);
    }
  }
  grid_sync_tree(gen, GP / 8);

  // h1 pointwise (chain step 1, h=0)
  {
    int e = bid * NT + tid;
    if (e < 15 * WU) {
      int c2 = e >> 9, u = e & (WU - 1);
      float gz = __ldcg(g_gxc + c2 * WCOLS + u);
      float gr = __ldcg(g_gxc + c2 * WCOLS + WU + u);
      float gn = __ldcg(g_gxc + c2 * WCOLS + 2 * WU + u);
      float brz = __ldg(bc + c2 * 3072 + WCOLS + u);
      float brr = __ldg(bc + c2 * 3072 + WCOLS + WU + u);
      float brn = __ldg(bc + c2 * 3072 + WCOLS + 2 * WU + u);
      float z = sigmoidf_(gz + brz);
      float r = sigmoidf_(gr + brr);
      float hh = tanhf_(gn + r * brn);
      g_h1[e] = (1.0f - z) * hh;
    }
  }
  grid_sync_tree(gen, GP / 8);

  // phase B: ghp[ci][col] = h1[ci] . rkc[ci][:,col] + b_r  (row-quarter split)
  {
    const float *wp = rkc + (size_t)ci * (WU * WCOLS) + (size_t)(qtr * 128) * WCOLS + col;
    const float *hp = g_h1 + ci * WU + qtr * 128;
    float a[16];
#pragma unroll
    for (int j = 0; j < 16; ++j) a[j] = 0.0f;
    for (int r = 0; r < 128; r += 16) {
#pragma unroll
      for (int j = 0; j < 16; ++j)
        a[j] = fmaf(__ldcg(hp + r + j), __ldcs(wp + (size_t)(r + j) * WCOLS), a[j]);
    }
    float s = 0.0f;
#pragma unroll
    for (int j = 0; j < 16; ++j) s += a[j];
    sm_part[warp][lane] = s;
    __syncthreads();
    if ((warp & 3) == 0) {
      float tot = sm_part[warp][lane] + sm_part[warp + 1][lane] +
                  sm_part[warp + 2][lane] + sm_part[warp + 3][lane];
      g_ghp[ci * WCOLS + col] = tot + __ldg(bc + ci * 3072 + WCOLS + col);
    }
  }
}

// =====================================================================
// GRU0 kernel: 16-CTA cluster, GT=256 (8 warps, 4 units/warp), ALL
// recurrent weights in registers. NEW k-slicing: each 8-lane group owns
// ONE unit; lane (lg = lane&7) covers k = lg*4 + j*32 (j=0..15).
// Byte addresses (lg*16 + j*128) are conflict-free (8 lanes x 16B
// contiguous per j, 4-group broadcast). Gate reduction is a 3-level
// butterfly within the 8-lane group (vs 6-level quad_reduce before).
// Per-step sync: b64-packed scalar st.async + tx-counted mbarrier,
// double-buffered h (WAR-safe, unchanged from the verified R10 path).
// =====================================================================
#define SWA_FLOATS (32 * 3 * WU)   // 49152 floats staging
#define GRU0_SMEM ((SWA_FLOATS + 2 * WU + WU + 4) * 4)

__global__ void __launch_bounds__(GT, 1) gru0_kernel(
    const float *__restrict__ lin, const float *__restrict__ k0,
    const float *__restrict__ rk0, const float *__restrict__ b0,
    float *__restrict__ lout)
{
  extern __shared__ float sm[];
  float *swA = sm;                        // [u][g][k] staging (dead after init)
  float *sh  = sm + SWA_FLOATS;           // [2][512] double-buffered h
  float *sx0 = sh + 2 * WU;               // [512]
  // mbar[2] after sx0

  unsigned rank;
  asm("mov.u32 %0, %%cluster_ctarank;" : "=r"(rank));
  const int tid = threadIdx.x, warp = tid >> 5, lane = tid & 31;
  const int base = (int)rank * 32;

  const uint32_t sm_u32 = (uint32_t)__cvta_generic_to_shared(sm);
  const uint32_t sh_u32 = sm_u32 + SWA_FLOATS * 4;
  const uint32_t mbar_u32 = sh_u32 + (2 * WU + WU) * 4;

  for (int i = tid; i < WU; i += GT) sx0[i] = __ldg(lin + 16 * i);
  for (int i = tid; i < 2 * WU; i += GT) sh[i] = 0.0f;
  // stage this CTA's 96 rec columns into SMEM, transposed to [u][g][k]
  for (int idx = tid; idx < 96 * WU; idx += GT) {
    int k = idx / 96, c2 = idx - k * 96;
    int g = c2 >> 5, u = c2 & 31;
    swA[(u * 3 + g) * WU + k] = __ldg(rk0 + (size_t)k * WCOLS + g * WU + base + u);
  }
  if (tid == 0) {
    mbar_init(mbar_u32, 1);
    mbar_init(mbar_u32 + 8, 1);
    mbar_expect_tx(mbar_u32, 2048);
    mbar_expect_tx(mbar_u32 + 8, 2048);
  }

  // lane mapping: myu = lane>>3 (unit within warp), lg = lane&7 (k slice)
  const bool h16 = (lane & 16) != 0;
  const int myu = lane >> 3;
  const int lg  = lane & 7;
  const int gu = base + warp * 4 + myu;
  const float kz  = __ldg(k0 + gu);
  const float kr  = __ldg(k0 + WU + gu);
  const float kn  = __ldg(k0 + 2 * WU + gu);
  const float cbz = __ldg(b0 + gu) + __ldg(b0 + WCOLS + gu);
  const float cbr = __ldg(b0 + WU + gu) + __ldg(b0 + WCOLS + WU + gu);
  const float bin = __ldg(b0 + 2 * WU + gu);
  const float brn = __ldg(b0 + WCOLS + 2 * WU + gu);

  __syncthreads();

  // weights into registers: W[j][g] covers k = j*32 + lg*4 .. +3 for unit gu
  ulonglong2 W[16][3];
#pragma unroll
  for (int j = 0; j < 16; ++j) {
#pragma unroll
    for (int g = 0; g < 3; ++g) {
      W[j][g] = *(const ulonglong2 *)(
          swA + (gu - base) * 3 * WU + g * WU + j * 32 + lg * 4);
    }
  }

  // b64 pair store targets: sender lanes 0-7 (units u0,u1) and 16-23 (u2,u3).
  const bool sender = (lane & 8) == 0;
  const int gu_pair = base + warp * 4 + (h16 ? 2 : 0);
  const unsigned tr0 = (unsigned)(lg * 2);
  const unsigned tr1 = tr0 + 1;
  uint32_t ra0[2], ra1[2], rm0[2], rm1[2];
#pragma unroll
  for (int b = 0; b < 2; ++b) {
    uint32_t loff = sh_u32 + ((unsigned)(b * WU + gu_pair) << 2);
    uint32_t moff = mbar_u32 + 8 * b;
    ra0[b] = mapa_u32(loff, tr0);
    ra1[b] = mapa_u32(loff, tr1);
    rm0[b] = mapa_u32(moff, tr0);
    rm1[b] = mapa_u32(moff, tr1);
  }
  uint32_t ph0 = 0, ph1 = 0;

  cluster_sync_();  // all mbars initialized, all h buffers zeroed

  for (int t = 0; t < WU; ++t) {
    const int p = t & 1;
    if (t) {
      const uint32_t mb = mbar_u32 + 8 * p;
      if (p) { mbar_wait(mb, ph1); ph1 ^= 1; }
      else   { mbar_wait(mb, ph0); ph0 ^= 1; }
      if (tid == 0) mbar_expect_tx(mb, 2048);  // re-arm for next fill of p
    }
    const float *hb = sh + p * WU;
    const float hold = hb[gu];

    u64 az = 0, ar = 0, an = 0;
#pragma unroll
    for (int j = 0; j < 16; ++j) {
      ulonglong2 hvj = *(const ulonglong2 *)(hb + j * 32 + lg * 4);
      ffma2(az, hvj.x, W[j][0].x); ffma2(az, hvj.y, W[j][0].y);
      ffma2(ar, hvj.x, W[j][1].x); ffma2(ar, hvj.y, W[j][1].y);
      ffma2(an, hvj.x, W[j][2].x); ffma2(an, hvj.y, W[j][2].y);
    }
    float dz = hsum2(az), dr = hsum2(ar), dn = hsum2(an);
#pragma unroll
    for (int o = 4; o; o >>= 1) {
      dz += __shfl_xor_sync(0xffffffffu, dz, o);
      dr += __shfl_xor_sync(0xffffffffu, dr, o);
      dn += __shfl_xor_sync(0xffffffffu, dn, o);
    }

    float xt = sx0[t];
    float z  = sigf_fast(fmaf(xt, kz, cbz) + dz);
    float r  = sigf_fast(fmaf(xt, kr, cbr) + dr);
    float hh = tanhf_fast(fmaf(xt, kn, bin) + r * (dn + brn));
    float hnew = hh + z * (hold - hh);

    // pair-pack: groups 0/2 hold (even unit, odd unit)
    float oth = __shfl_xor_sync(0xffffffffu, hnew, 8);
    u64 pk = (u64)__float_as_uint(hnew) | ((u64)__float_as_uint(oth) << 32);

    // tid0's expect_tx (and all buffer-p reads) must precede our stores:
    // our stores gate every CTA's entry into step t+1.
    __syncthreads();

    if (t < WU - 1) {
      if (sender) {
        st_async_b64(ra0[p ^ 1], rm0[p ^ 1], pk);
        st_async_b64(ra1[p ^ 1], rm1[p ^ 1], pk);
      }
    } else {
      if (lg == 0) lout[gu] = hnew;  // y0 (lanes 0,8,16,24 cover the 4 units)
    }
  }
}

// =====================================================================
// Chain kernel (192 CTAs persistent, 2/SM): 15 serial 2-step GRUs.
// 4-way row split per column block (48 blocks x 4 quarters). ONE
// grid_sync per step; every CTA redundantly computes y into local SMEM.
// =====================================================================
__global__ void __launch_bounds__(NT, 2) chain_kernel(
    float *__restrict__ lout, const float *__restrict__ kc,
    const float *__restrict__ bc)
{
  __shared__ float sy[WU];
  __shared__ float sm_part[NW * 32];
  const int bid = blockIdx.x, tid = threadIdx.x;
  const int warp = tid >> 5, lane = tid & 31;
  unsigned gen = *(volatile unsigned *)&g_gen;

  for (int i = tid; i < WU; i += NT) sy[i] = __ldcg(lout + i);  // y0
  __syncthreads();

  const int cb = bid >> 2, qtr = bid & 3;
  const int col = cb * 32 + lane;

  for (int ci = 0; ci < 15; ++ci) {
    const int buf = ci & 1;
    float *gp = g_gpart + buf * 4 * WCOLS;
    // pass1: gp[qtr][col] = partial of y_prev . kc[ci][:,col] over 128 rows
    {
      const float *wp = kc + (size_t)ci * (WU * WCOLS) + col;
      float acc = 0.0f;
      for (int r0 = warp; r0 < 128; r0 += NW) {
        int r = qtr * 128 + r0;
        acc = fmaf(sy[r], __ldg(wp + (size_t)r * WCOLS), acc);
      }
      sm_part[warp * 32 + lane] = acc;
      __syncthreads();
      if (warp == 0) {
        float s = 0.0f;
#pragma unroll
        for (int w2 = 0; w2 < NW; ++w2) s += sm_part[w2 * 32 + lane];
        gp[qtr * WCOLS + col] = s;
      }
    }
    grid_sync_tree(gen, GC / 8);
    // y-compute (all CTAs, redundant, into local sy)
    for (int u = tid; u < WU; u += NT) {
      float gxz = __ldcg(gp + u) + __ldcg(gp + WCOLS + u) +
                  __ldcg(gp + 2 * WCOLS + u) + __ldcg(gp + 3 * WCOLS + u) +
                  __ldg(bc + ci * 3072 + u);
      float gxr = __ldcg(gp + WU + u) + __ldcg(gp + WCOLS + WU + u) +
                  __ldcg(gp + 2 * WCOLS + WU + u) + __ldcg(gp + 3 * WCOLS + WU + u) +
                  __ldg(bc + ci * 3072 + WU + u);
      float gxh = __ldcg(gp + 2 * WU + u) + __ldcg(gp + WCOLS + 2 * WU + u) +
                  __ldcg(gp + 2 * WCOLS + 2 * WU + u) + __ldcg(gp + 3 * WCOLS + 2 * WU + u) +
                  __ldg(bc + ci * 3072 + 2 * WU + u);
      float ghz = __ldcg(g_ghp + ci * WCOLS + u);
      float ghr = __ldcg(g_ghp + ci * WCOLS + WU + u);
      float ghn = __ldcg(g_ghp + ci * WCOLS + 2 * WU + u);
      float h1v = __ldcg(g_h1 + ci * WU + u);
      float z = sigmoidf_(gxz + ghz);
      float r = sigmoidf_(gxr + ghr);
      float hh = tanhf_(gxh + r * ghn);
      float y = z * h1v + (1.0f - z) * hh;
      sy[u] = y;
      if (bid == 0) lout[(ci + 1) * WU + u] = y;
    }
    __syncthreads();  // sy ready for next pass1 (CTA-local)
  }
}

// =====================================================================
// Host launcher: gru0(l) [stream 0] overlaps phases(l) [s2] — both
// depend only on chain(l-1). gru0 is enqueued FIRST so its 16-SM
// cluster places before phases' 240 CTAs fill the chip. chain(l)
// joins both. Final join back to stream 0.
// =====================================================================
extern "C" void kernel_launch(void *const *d_in, const int *in_sizes, int n_in,
                              void *d_out, int out_size) {
  (void)in_sizes; (void)n_in; (void)out_size;
  const float *x = (const float *)d_in[0];
  const float *K0[3]  = {(const float *)d_in[1],  (const float *)d_in[7],  (const float *)d_in[13]};
  const float *RK0[3] = {(const float *)d_in[2],  (const float *)d_in[8],  (const float *)d_in[14]};
  const float *B0[3]  = {(const float *)d_in[3],  (const float *)d_in[9],  (const float *)d_in[15]};
  const float *KC[3]  = {(const float *)d_in[4],  (const float *)d_in[10], (const float *)d_in[16]};
  const float *RKC[3] = {(const float *)d_in[5],  (const float *)d_in[11], (const float *)d_in[17]};
  const float *BC[3]  = {(const float *)d_in[6],  (const float *)d_in[12], (const float *)d_in[18]};

  float *pA = nullptr, *pB = nullptr;
  cudaGetSymbolAddress((void **)&pA, g_bufA);
  cudaGetSymbolAddress((void **)&pB, g_bufB);

  cudaFuncSetAttribute(gru0_kernel, cudaFuncAttributeMaxDynamicSharedMemorySize, GRU0_SMEM);
  cudaFuncSetAttribute(gru0_kernel, cudaFuncAttributeNonPortableClusterSizeAllowed, 1);

  const float *LIN[3] = {x, pA, pB};
  float *LOUT[3] = {pA, pB, (float *)d_out};

  cudaStream_t s2;
  cudaStreamCreateWithFlags(&s2, cudaStreamNonBlocking);

  cudaEvent_t evFork, evG[3], evC[3];
  cudaEventCreateWithFlags(&evFork, cudaEventDisableTiming);
  for (int l = 0; l < 3; ++l) {
    cudaEventCreateWithFlags(&evG[l], cudaEventDisableTiming);
    cudaEventCreateWithFlags(&evC[l], cudaEventDisableTiming);
  }

  // fork s2 from stream 0
  cudaEventRecord(evFork, 0);
  cudaStreamWaitEvent(s2, evFork, 0);

  for (int l = 0; l < 3; ++l) {
    if (l > 0) cudaStreamWaitEvent(0, evC[l - 1], 0);  // gru0(l) needs chain(l-1)

    // enqueue gru0 FIRST so the cluster places before phases fills SMs
    cudaLaunchConfig_t cfg = {};
    cfg.gridDim = dim3(CL, 1, 1);
    cfg.blockDim = dim3(GT, 1, 1);
    cfg.dynamicSmemBytes = GRU0_SMEM;
    cfg.stream = 0;
    cudaLaunchAttribute attrs[1];
    attrs[0].id = cudaLaunchAttributeClusterDimension;
    attrs[0].val.clusterDim = {CL, 1, 1};
    cfg.attrs = attrs;
    cfg.numAttrs = 1;
    cudaLaunchKernelEx(&cfg, gru0_kernel, LIN[l], K0[l], RK0[l], B0[l], LOUT[l]);
    cudaEventRecord(evG[l], 0);

    // phases concurrently on s2 (s2 already ordered after chain(l-1))
    phases_kernel<<<GP, NT, 0, s2>>>(LIN[l], KC[l], RKC[l], BC[l]);

    // chain joins gru0 + phases
    cudaStreamWaitEvent(s2, evG[l], 0);
    chain_kernel<<<GC, NT, 0, s2>>>(LOUT[l], KC[l], BC[l]);
    cudaEventRecord(evC[l], s2);
  }

  // join s2 back into stream 0 so the captured graph ends on chain(3)
  cudaStreamWaitEvent(0, evC[2], 0);

  cudaEventDestroy(evFork);
  for (int l = 0; l < 3; ++l) {
    cudaEventDestroy(evG[l]);
    cudaEventDestroy(evC[l]);
  }
  cudaStreamDestroy(s2);
}

// round 17
// speedup vs baseline: 1.0249x; 1.0249x over previous
#include <cuda_runtime.h>
#include <cstdint>

#define NT 384
#define NW 12
#define WU 512
#define WCOLS 1536
#define GP 240   // phases grid (720 jobs x 4 row-quarters = 2880 warps)
#define GC 192   // chain grid (48 col-blocks x 4 row-quarters)
#define CL 16    // GRU0 cluster size
#define GT 256   // GRU0 threads per CTA (8 warps, 4 units/warp)

typedef unsigned long long u64;

// ---------------- device scratch (static, no allocation) ----------------
__device__ float g_bufA[16 * WU];
__device__ float g_bufB[16 * WU];
__device__ float g_h1[15 * WU];
__device__ float g_ghp[15 * WCOLS];
__device__ float g_gxc[15 * WCOLS];
__device__ float g_gpart[8 * WCOLS];   // [ci&1][qtr][col]
__device__ unsigned g_cnt_grp[32];
__device__ unsigned g_cnt_root;
__device__ unsigned g_gen;

// Tree grid barrier: 8-CTA leaf groups -> root. All counters return to 0
// before g_gen publishes, so the zero-init invariant holds across launches.
__device__ __forceinline__ void grid_sync_tree(unsigned &gen, unsigned ngrp) {
  unsigned next = gen + 1u;
  __threadfence();
  __syncthreads();
  if (threadIdx.x == 0) {
    unsigned g = (unsigned)blockIdx.x >> 3;
    bool last = false;
    if (atomicAdd(&g_cnt_grp[g], 1u) == 7u) {
      if (atomicAdd(&g_cnt_root, 1u) == ngrp - 1u) last = true;
    }
    if (last) {
      for (unsigned i = 0; i < ngrp; ++i) g_cnt_grp[i] = 0u;
      g_cnt_root = 0u;
      __threadfence();
      atomicExch(&g_gen, next);
    } else {
      while ((int)(*(volatile unsigned *)&g_gen - next) < 0) { }
    }
  }
  gen = next;
  __syncthreads();
}

__device__ __forceinline__ float sigmoidf_(float x) {
  return 1.0f / (1.0f + __expf(-x));
}
__device__ __forceinline__ float tanhf_(float x) {
  float ax = fabsf(x);
  float e = __expf(-2.0f * ax);
  float t = (1.0f - e) / (1.0f + e);
  return copysignf(t, x);
}
__device__ __forceinline__ float sigf_fast(float x) {
  return __fdividef(1.0f, 1.0f + __expf(-x));
}
__device__ __forceinline__ float tanhf_fast(float x) {
  float ax = fabsf(x);
  float e = __expf(-2.0f * ax);
  float t = __fdividef(1.0f - e, 1.0f + e);
  return copysignf(t, x);
}

// ---------------- Blackwell helpers ----------------
__device__ __forceinline__ void ffma2(u64 &acc, u64 a, u64 b) {
  asm("fma.rn.f32x2 %0, %1, %2, %0;" : "+l"(acc) : "l"(a), "l"(b));
}
__device__ __forceinline__ float hsum2(u64 v) {
  float lo, hi;
  asm("mov.b64 {%0,%1}, %2;" : "=f"(lo), "=f"(hi) : "l"(v));
  return lo + hi;
}
__device__ __forceinline__ uint32_t mapa_u32(uint32_t laddr, unsigned rank) {
  uint32_t raddr;
  asm("mapa.shared::cluster.u32 %0, %1, %2;" : "=r"(raddr) : "r"(laddr), "r"(rank));
  return raddr;
}
__device__ __forceinline__ void st_async_b64(uint32_t raddr, uint32_t rmbar, u64 v) {
  asm volatile(
      "st.async.shared::cluster.mbarrier::complete_tx::bytes.b64 [%0], %1, [%2];"
      :: "r"(raddr), "l"(v), "r"(rmbar) : "memory");
}
__device__ __forceinline__ void mbar_init(uint32_t mbar, unsigned cnt) {
  asm volatile("mbarrier.init.shared.b64 [%0], %1;" :: "r"(mbar), "r"(cnt) : "memory");
}
__device__ __forceinline__ void mbar_expect_tx(uint32_t mbar, unsigned bytes) {
  asm volatile("mbarrier.arrive.expect_tx.shared.b64 _, [%0], %1;"
               :: "r"(mbar), "r"(bytes) : "memory");
}
__device__ __forceinline__ void mbar_wait(uint32_t mbar, uint32_t parity) {
  uint32_t done;
  asm volatile(
      "{\n\t.reg .pred p;\n\t"
      "mbarrier.try_wait.parity.acquire.cta.shared::cta.b64 p, [%1], %2;\n\t"
      "selp.b32 %0, 1, 0, p;\n\t}"
      : "=r"(done) : "r"(mbar), "r"(parity) : "memory");
  if (!done) {
    asm volatile(
        "{\n\t.reg .pred P1;\n\t"
        "WAIT_LOOP_%=:\n\t"
        "mbarrier.try_wait.parity.acquire.cta.shared::cta.b64 P1, [%0], %1, 0x989680;\n\t"
        "@P1 bra.uni WAIT_DONE_%=;\n\t"
        "bra.uni WAIT_LOOP_%=;\n\t"
        "WAIT_DONE_%=:\n\t}"
        :: "r"(mbar), "r"(parity) : "memory");
  }
}
__device__ __forceinline__ void cluster_sync_() {
  asm volatile("barrier.cluster.arrive.aligned;" ::: "memory");
  asm volatile("barrier.cluster.wait.aligned;" ::: "memory");
}

// 4-unit paired warp reduction. Lane layout after reduce:
//   lanes 0-7 hold full sum of v0, 8-15 of v1, 16-23 of v2, 24-31 of v3.
__device__ __forceinline__ float quad_reduce(float v0, float v1, float v2,
                                             float v3, bool h16, bool h8) {
  float A  = h16 ? v2 : v0;
  float Ao = h16 ? v0 : v2;
  A += __shfl_xor_sync(0xffffffffu, Ao, 16);
  float B  = h16 ? v3 : v1;
  float Bo = h16 ? v1 : v3;
  B += __shfl_xor_sync(0xffffffffu, Bo, 16);
  float C  = h8 ? B : A;
  float Co = h8 ? A : B;
  C += __shfl_xor_sync(0xffffffffu, Co, 8);
  C += __shfl_xor_sync(0xffffffffu, C, 4);
  C += __shfl_xor_sync(0xffffffffu, C, 2);
  C += __shfl_xor_sync(0xffffffffu, C, 1);
  return C;
}

// =====================================================================
// Phases kernel (GP=240 CTAs, 2/SM): gxc -> h1 -> ghp for all 15 chain GRUs
// Each of the 720 column jobs split into 4 row-quarters (4 warps/job).
// rkc is read-once -> __ldcs (evict-first) so kc stays resident in L2
// for the chain kernel's re-reads.
// =====================================================================
__global__ void __launch_bounds__(NT, 2) phases_kernel(
    const float *__restrict__ lin, const float *__restrict__ kc,
    const float *__restrict__ rkc, const float *__restrict__ bc)
{
  __shared__ float sm_x1[WU];
  __shared__ float sm_part[NW][32];
  const int bid = blockIdx.x, tid = threadIdx.x;
  const int warp = tid >> 5, lane = tid & 31;
  unsigned gen = *(volatile unsigned *)&g_gen;

  for (int i = tid; i < WU; i += NT) sm_x1[i] = __ldcg(lin + i * 16 + 1);
  __syncthreads();

  const int wg = bid * NW + warp;        // 0..2879
  const int job = wg >> 2, qtr = wg & 3; // 720 jobs x 4 quarters
  const int ci = job / 48;
  const int col = (job - ci * 48) * 32 + lane;

  // phase A: gxc[ci][col] = x1 . kc[ci][:,col] + b_i  (row-quarter split)
  {
    const float *wp = kc + (size_t)ci * (WU * WCOLS) + (size_t)(qtr * 128) * WCOLS + col;
    float a[16];
#pragma unroll
    for (int j = 0; j < 16; ++j) a[j] = 0.0f;
    for (int r = 0; r < 128; r += 16) {
#pragma unroll
      for (int j = 0; j < 16; ++j)
        a[j] = fmaf(sm_x1[qtr * 128 + r + j], __ldg(wp + (size_t)(r + j) * WCOLS), a[j]);
    }
    float s = 0.0f;
#pragma unroll
    for (int j = 0; j < 16; ++j) s += a[j];
    sm_part[warp][lane] = s;
    __syncthreads();
    if ((warp & 3) == 0) {
      float tot = sm_part[warp][lane] + sm_part[warp + 1][lane] +
                  sm_part[warp + 2][lane] + sm_part[warp + 3][lane];
      g_gxc[ci * WCOLS + col] = tot + __ldg(bc + ci * 3072 + col);
    }
  }
  grid_sync_tree(gen, GP / 8);

  // h1 pointwise (chain step 1, h=0)
  {
    int e = bid * NT + tid;
    if (e < 15 * WU) {
      int c2 = e >> 9, u = e & (WU - 1);
      float gz = __ldcg(g_gxc + c2 * WCOLS + u);
      float gr = __ldcg(g_gxc + c2 * WCOLS + WU + u);
      float gn = __ldcg(g_gxc + c2 * WCOLS + 2 * WU + u);
      float brz = __ldg(bc + c2 * 3072 + WCOLS + u);
      float brr = __ldg(bc + c2 * 3072 + WCOLS + WU + u);
      float brn = __ldg(bc + c2 * 3072 + WCOLS + 2 * WU + u);
      float z = sigmoidf_(gz + brz);
      float r = sigmoidf_(gr + brr);
      float hh = tanhf_(gn + r * brn);
      g_h1[e] = (1.0f - z) * hh;
    }
  }
  grid_sync_tree(gen, GP / 8);

  // phase B: ghp[ci][col] = h1[ci] . rkc[ci][:,col] + b_r  (row-quarter split)
  {
    const float *wp = rkc + (size_t)ci * (WU * WCOLS) + (size_t)(qtr * 128) * WCOLS + col;
    const float *hp = g_h1 + ci * WU + qtr * 128;
    float a[16];
#pragma unroll
    for (int j = 0; j < 16; ++j) a[j] = 0.0f;
    for (int r = 0; r < 128; r += 16) {
#pragma unroll
      for (int j = 0; j < 16; ++j)
        a[j] = fmaf(__ldcg(hp + r + j), __ldcs(wp + (size_t)(r + j) * WCOLS), a[j]);
    }
    float s = 0.0f;
#pragma unroll
    for (int j = 0; j < 16; ++j) s += a[j];
    sm_part[warp][lane] = s;
    __syncthreads();
    if ((warp & 3) == 0) {
      float tot = sm_part[warp][lane] + sm_part[warp + 1][lane] +
                  sm_part[warp + 2][lane] + sm_part[warp + 3][lane];
      g_ghp[ci * WCOLS + col] = tot + __ldg(bc + ci * 3072 + WCOLS + col);
    }
  }
}

// =====================================================================
// GRU0 kernel (R14 inner loop + 2 critical-path cuts): 16-CTA cluster,
// GT=256 (8 warps, 4 units/warp), ALL weights in registers, conflict-
// free hv loads (lane*16B), 6-level quad_reduce.
//  (1) hold carried in a register: h_old[gu] == our previous hnew,
//      so the dependent post-wake LDS is deleted.
//  (2) __syncthreads moved to right after the hv loads: all buffer-p
//      reads (hv; hold is a register) and tid0's re-arm precede it, so
//      senders may store as soon as THEIR gates finish (no wait on the
//      slowest warp's compute). Ordering: reads < sync < stores, and
//      re-arm < sync < stores — WAR/expect_tx proofs unchanged.
// Per-step sync: b64-packed scalar st.async + tx-counted mbarrier,
// double-buffered h.
// =====================================================================
#define SWA_FLOATS (32 * 3 * WU)   // 49152 floats staging
#define GRU0_SMEM ((SWA_FLOATS + 2 * WU + WU + 4) * 4)

__global__ void __launch_bounds__(GT, 1) gru0_kernel(
    const float *__restrict__ lin, const float *__restrict__ k0,
    const float *__restrict__ rk0, const float *__restrict__ b0,
    float *__restrict__ lout)
{
  extern __shared__ float sm[];
  float *swA = sm;                        // [u][g][k] staging (dead after init)
  float *sh  = sm + SWA_FLOATS;           // [2][512] double-buffered h
  float *sx0 = sh + 2 * WU;               // [512]
  // mbar[2] after sx0

  unsigned rank;
  asm("mov.u32 %0, %%cluster_ctarank;" : "=r"(rank));
  const int tid = threadIdx.x, warp = tid >> 5, lane = tid & 31;
  const int base = (int)rank * 32;

  const uint32_t sm_u32 = (uint32_t)__cvta_generic_to_shared(sm);
  const uint32_t sh_u32 = sm_u32 + SWA_FLOATS * 4;
  const uint32_t mbar_u32 = sh_u32 + (2 * WU + WU) * 4;

  for (int i = tid; i < WU; i += GT) sx0[i] = __ldg(lin + 16 * i);
  for (int i = tid; i < 2 * WU; i += GT) sh[i] = 0.0f;
  // stage this CTA's 96 rec columns into SMEM, transposed to [u][g][k]
  for (int idx = tid; idx < 96 * WU; idx += GT) {
    int k = idx / 96, c2 = idx - k * 96;
    int g = c2 >> 5, u = c2 & 31;
    swA[(u * 3 + g) * WU + k] = __ldg(rk0 + (size_t)k * WCOLS + g * WU + base + u);
  }
  if (tid == 0) {
    mbar_init(mbar_u32, 1);
    mbar_init(mbar_u32 + 8, 1);
    mbar_expect_tx(mbar_u32, 2048);
    mbar_expect_tx(mbar_u32 + 8, 2048);
  }

  // lane group -> unit: myu = lane>>3 within this warp's 4 units
  const bool h16 = (lane & 16) != 0;
  const bool h8  = (lane & 8) != 0;
  const int myu = lane >> 3;
  const int gu = base + warp * 4 + myu;
  const float kz  = __ldg(k0 + gu);
  const float kr  = __ldg(k0 + WU + gu);
  const float kn  = __ldg(k0 + 2 * WU + gu);
  const float cbz = __ldg(b0 + gu) + __ldg(b0 + WCOLS + gu);
  const float cbr = __ldg(b0 + WU + gu) + __ldg(b0 + WCOLS + WU + gu);
  const float bin = __ldg(b0 + 2 * WU + gu);
  const float brn = __ldg(b0 + WCOLS + 2 * WU + gu);

  __syncthreads();

  // all weights into registers: W[c][u][g], k = c*128 + lane*4 .. +4
  ulonglong2 W[4][4][3];
#pragma unroll
  for (int c = 0; c < 4; ++c) {
#pragma unroll
    for (int uu = 0; uu < 4; ++uu) {
#pragma unroll
      for (int g = 0; g < 3; ++g) {
        W[c][uu][g] = *(const ulonglong2 *)(
            swA + ((warp * 4 + uu) * 3 + g) * WU + c * 128 + lane * 4);
      }
    }
  }

  // b64 pair store targets: sender lanes 0-7 (units u0,u1) and 16-23 (u2,u3).
  const bool sender = (lane & 8) == 0;
  const int gu_pair = base + warp * 4 + (h16 ? 2 : 0);
  const unsigned tr0 = (unsigned)((lane & 7) * 2);
  const unsigned tr1 = tr0 + 1;
  uint32_t ra0[2], ra1[2], rm0[2], rm1[2];
#pragma unroll
  for (int b = 0; b < 2; ++b) {
    uint32_t loff = sh_u32 + ((unsigned)(b * WU + gu_pair) << 2);
    uint32_t moff = mbar_u32 + 8 * b;
    ra0[b] = mapa_u32(loff, tr0);
    ra1[b] = mapa_u32(loff, tr1);
    rm0[b] = mapa_u32(moff, tr0);
    rm1[b] = mapa_u32(moff, tr1);
  }
  uint32_t ph0 = 0, ph1 = 0;
  float hprev = 0.0f;   // our unit's h (h0 = 0)

  cluster_sync_();  // all mbars initialized, all h buffers zeroed

  for (int t = 0; t < WU; ++t) {
    const int p = t & 1;
    if (t) {
      const uint32_t mb = mbar_u32 + 8 * p;
      if (p) { mbar_wait(mb, ph1); ph1 ^= 1; }
      else   { mbar_wait(mb, ph0); ph0 ^= 1; }
      if (tid == 0) mbar_expect_tx(mb, 2048);  // re-arm for next fill of p
    }
    const float *hb = sh + p * WU;
    ulonglong2 hv[4];
#pragma unroll
    for (int c = 0; c < 4; ++c)
      hv[c] = *(const ulonglong2 *)(hb + c * 128 + lane * 4);

    // All buffer-p reads done; re-arm done. Senders may store as soon as
    // their own compute finishes — no post-compute barrier needed.
    __syncthreads();

    float s[4][3];
#pragma unroll
    for (int uu = 0; uu < 4; ++uu) {
      u64 az = 0, ar = 0, an = 0;
#pragma unroll
      for (int c = 0; c < 4; ++c) {
        ffma2(az, hv[c].x, W[c][uu][0].x); ffma2(az, hv[c].y, W[c][uu][0].y);
        ffma2(ar, hv[c].x, W[c][uu][1].x); ffma2(ar, hv[c].y, W[c][uu][1].y);
        ffma2(an, hv[c].x, W[c][uu][2].x); ffma2(an, hv[c].y, W[c][uu][2].y);
      }
      s[uu][0] = hsum2(az);
      s[uu][1] = hsum2(ar);
      s[uu][2] = hsum2(an);
    }
    float dz = quad_reduce(s[0][0], s[1][0], s[2][0], s[3][0], h16, h8);
    float dr = quad_reduce(s[0][1], s[1][1], s[2][1], s[3][1], h16, h8);
    float dn = quad_reduce(s[0][2], s[1][2], s[2][2], s[3][2], h16, h8);

    float xt = sx0[t];
    float z  = sigf_fast(fmaf(xt, kz, cbz) + dz);
    float r  = sigf_fast(fmaf(xt, kr, cbr) + dr);
    float hh = tanhf_fast(fmaf(xt, kn, bin) + r * (dn + brn));
    float hnew = hh + z * (hprev - hh);
    hprev = hnew;

    // pair-pack: groups 0/2 hold (even unit, odd unit)
    float oth = __shfl_xor_sync(0xffffffffu, hnew, 8);
    u64 pk = (u64)__float_as_uint(hnew) | ((u64)__float_as_uint(oth) << 32);

    if (t < WU - 1) {
      if (sender) {
        st_async_b64(ra0[p ^ 1], rm0[p ^ 1], pk);
        st_async_b64(ra1[p ^ 1], rm1[p ^ 1], pk);
      }
    } else {
      if ((lane & 7) == 0) lout[gu] = hnew;  // y0 (lanes 0,8,16,24)
    }
  }
}

// =====================================================================
// Chain kernel (192 CTAs persistent, 2/SM): 15 serial 2-step GRUs.
// 4-way row split per column block (48 blocks x 4 quarters). ONE
// grid_sync per step; every CTA redundantly computes y into local SMEM.
// =====================================================================
__global__ void __launch_bounds__(NT, 2) chain_kernel(
    float *__restrict__ lout, const float *__restrict__ kc,
    const float *__restrict__ bc)
{
  __shared__ float sy[WU];
  __shared__ float sm_part[NW * 32];
  const int bid = blockIdx.x, tid = threadIdx.x;
  const int warp = tid >> 5, lane = tid & 31;
  unsigned gen = *(volatile unsigned *)&g_gen;

  for (int i = tid; i < WU; i += NT) sy[i] = __ldcg(lout + i);  // y0
  __syncthreads();

  const int cb = bid >> 2, qtr = bid & 3;
  const int col = cb * 32 + lane;

  for (int ci = 0; ci < 15; ++ci) {
    const int buf = ci & 1;
    float *gp = g_gpart + buf * 4 * WCOLS;
    // pass1: gp[qtr][col] = partial of y_prev . kc[ci][:,col] over 128 rows
    {
      const float *wp = kc + (size_t)ci * (WU * WCOLS) + col;
      float acc = 0.0f;
      for (int r0 = warp; r0 < 128; r0 += NW) {
        int r = qtr * 128 + r0;
        acc = fmaf(sy[r], __ldg(wp + (size_t)r * WCOLS), acc);
      }
      sm_part[warp * 32 + lane] = acc;
      __syncthreads();
      if (warp == 0) {
        float s = 0.0f;
#pragma unroll
        for (int w2 = 0; w2 < NW; ++w2) s += sm_part[w2 * 32 + lane];
        gp[qtr * WCOLS + col] = s;
      }
    }
    grid_sync_tree(gen, GC / 8);
    // y-compute (all CTAs, redundant, into local sy)
    for (int u = tid; u < WU; u += NT) {
      float gxz = __ldcg(gp + u) + __ldcg(gp + WCOLS + u) +
                  __ldcg(gp + 2 * WCOLS + u) + __ldcg(gp + 3 * WCOLS + u) +
                  __ldg(bc + ci * 3072 + u);
      float gxr = __ldcg(gp + WU + u) + __ldcg(gp + WCOLS + WU + u) +
                  __ldcg(gp + 2 * WCOLS + WU + u) + __ldcg(gp + 3 * WCOLS + WU + u) +
                  __ldg(bc + ci * 3072 + WU + u);
      float gxh = __ldcg(gp + 2 * WU + u) + __ldcg(gp + WCOLS + 2 * WU + u) +
                  __ldcg(gp + 2 * WCOLS + 2 * WU + u) + __ldcg(gp + 3 * WCOLS + 2 * WU + u) +
                  __ldg(bc + ci * 3072 + 2 * WU + u);
      float ghz = __ldcg(g_ghp + ci * WCOLS + u);
      float ghr = __ldcg(g_ghp + ci * WCOLS + WU + u);
      float ghn = __ldcg(g_ghp + ci * WCOLS + 2 * WU + u);
      float h1v = __ldcg(g_h1 + ci * WU + u);
      float z = sigmoidf_(gxz + ghz);
      float r = sigmoidf_(gxr + ghr);
      float hh = tanhf_(gxh + r * ghn);
      float y = z * h1v + (1.0f - z) * hh;
      sy[u] = y;
      if (bid == 0) lout[(ci + 1) * WU + u] = y;
    }
    __syncthreads();  // sy ready for next pass1 (CTA-local)
  }
}

// =====================================================================
// Host launcher: gru0(l) [stream 0] overlaps phases(l) [s2] — both
// depend only on chain(l-1). gru0 is enqueued FIRST so its 16-SM
// cluster places before phases' 240 CTAs fill the chip. chain(l)
// joins both. Final join back to stream 0.
// =====================================================================
extern "C" void kernel_launch(void *const *d_in, const int *in_sizes, int n_in,
                              void *d_out, int out_size) {
  (void)in_sizes; (void)n_in; (void)out_size;
  const float *x = (const float *)d_in[0];
  const float *K0[3]  = {(const float *)d_in[1],  (const float *)d_in[7],  (const float *)d_in[13]};
  const float *RK0[3] = {(const float *)d_in[2],  (const float *)d_in[8],  (const float *)d_in[14]};
  const float *B0[3]  = {(const float *)d_in[3],  (const float *)d_in[9],  (const float *)d_in[15]};
  const float *KC[3]  = {(const float *)d_in[4],  (const float *)d_in[10], (const float *)d_in[16]};
  const float *RKC[3] = {(const float *)d_in[5],  (const float *)d_in[11], (const float *)d_in[17]};
  const float *BC[3]  = {(const float *)d_in[6],  (const float *)d_in[12], (const float *)d_in[18]};

  float *pA = nullptr, *pB = nullptr;
  cudaGetSymbolAddress((void **)&pA, g_bufA);
  cudaGetSymbolAddress((void **)&pB, g_bufB);

  cudaFuncSetAttribute(gru0_kernel, cudaFuncAttributeMaxDynamicSharedMemorySize, GRU0_SMEM);
  cudaFuncSetAttribute(gru0_kernel, cudaFuncAttributeNonPortableClusterSizeAllowed, 1);

  const float *LIN[3] = {x, pA, pB};
  float *LOUT[3] = {pA, pB, (float *)d_out};

  cudaStream_t s2;
  cudaStreamCreateWithFlags(&s2, cudaStreamNonBlocking);

  cudaEvent_t evFork, evG[3], evC[3];
  cudaEventCreateWithFlags(&evFork, cudaEventDisableTiming);
  for (int l = 0; l < 3; ++l) {
    cudaEventCreateWithFlags(&evG[l], cudaEventDisableTiming);
    cudaEventCreateWithFlags(&evC[l], cudaEventDisableTiming);
  }

  // fork s2 from stream 0
  cudaEventRecord(evFork, 0);
  cudaStreamWaitEvent(s2, evFork, 0);

  for (int l = 0; l < 3; ++l) {
    if (l > 0) cudaStreamWaitEvent(0, evC[l - 1], 0);  // gru0(l) needs chain(l-1)

    // enqueue gru0 FIRST so the cluster places before phases fills SMs
    cudaLaunchConfig_t cfg = {};
    cfg.gridDim = dim3(CL, 1, 1);
    cfg.blockDim = dim3(GT, 1, 1);
    cfg.dynamicSmemBytes = GRU0_SMEM;
    cfg.stream = 0;
    cudaLaunchAttribute attrs[1];
    attrs[0].id = cudaLaunchAttributeClusterDimension;
    attrs[0].val.clusterDim = {CL, 1, 1};
    cfg.attrs = attrs;
    cfg.numAttrs = 1;
    cudaLaunchKernelEx(&cfg, gru0_kernel, LIN[l], K0[l], RK0[l], B0[l], LOUT[l]);
    cudaEventRecord(evG[l], 0);

    // phases concurrently on s2 (s2 already ordered after chain(l-1))
    phases_kernel<<<GP, NT, 0, s2>>>(LIN[l], KC[l], RKC[l], BC[l]);

    // chain joins gru0 + phases
    cudaStreamWaitEvent(s2, evG[l], 0);
    chain_kernel<<<GC, NT, 0, s2>>>(LOUT[l], KC[l], BC[l]);
    cudaEventRecord(evC[l], s2);
  }

  // join s2 back into stream 0 so the captured graph ends on chain(3)
  cudaStreamWaitEvent(0, evC[2], 0);

  cudaEventDestroy(evFork);
  for (int l = 0; l < 3; ++l) {
    cudaEventDestroy(evG[l]);
    cudaEventDestroy(evC[l]);
  }
  cudaStreamDestroy(s2);
}